// round 15
// baseline (speedup 1.0000x reference)
#include <cuda_runtime.h>
#include <cuda_fp16.h>
#include <math.h>

#define B_  2
#define S_  2048
#define D_  1024
#define H_  16
#define HD_ 64
#define EPS_ 1e-6f
// (1/sqrt(hd)) * log2(e), folded into q during fused rmsnorm
#define QFOLD 0.18033688011112042f

// Scratch (__device__ globals: allocation-free rule)
__device__ __half g_qkvh[B_ * S_ * 3 * D_];  // qkv fp16 (post-norm q,k)
__device__ __half g_oh [B_ * S_ * D_];       // attention out, fp16
__device__ __half g_xh [B_ * S_ * D_];       // x, fp16
__device__ __half g_wqh[D_ * 3 * D_];        // Wqkv [D][3D] fp16 (row-major)
__device__ __half g_woh[D_ * D_];            // Wout [D][D]  fp16 (row-major)

// ---------------------------------------------------------------------------
__device__ __forceinline__ void mma_f16(float* c, const unsigned* a, const unsigned* b) {
    asm volatile(
        "mma.sync.aligned.m16n8k16.row.col.f32.f16.f16.f32 "
        "{%0,%1,%2,%3}, {%4,%5,%6,%7}, {%8,%9}, {%0,%1,%2,%3};"
        : "+f"(c[0]), "+f"(c[1]), "+f"(c[2]), "+f"(c[3])
        : "r"(a[0]), "r"(a[1]), "r"(a[2]), "r"(a[3]), "r"(b[0]), "r"(b[1]));
}
__device__ __forceinline__ void ldsm4(unsigned& r0, unsigned& r1, unsigned& r2,
                                      unsigned& r3, unsigned addr) {
    asm volatile("ldmatrix.sync.aligned.m8n8.x4.shared.b16 {%0,%1,%2,%3}, [%4];"
        : "=r"(r0), "=r"(r1), "=r"(r2), "=r"(r3) : "r"(addr));
}
__device__ __forceinline__ void ldsm4t(unsigned& r0, unsigned& r1, unsigned& r2,
                                       unsigned& r3, unsigned addr) {
    asm volatile("ldmatrix.sync.aligned.m8n8.x4.trans.shared.b16 {%0,%1,%2,%3}, [%4];"
        : "=r"(r0), "=r"(r1), "=r"(r2), "=r"(r3) : "r"(addr));
}
__device__ __forceinline__ unsigned sptr(const void* p) {
    return (unsigned)__cvta_generic_to_shared(p);
}
__device__ __forceinline__ void cpa16(unsigned dst, const void* src) {
    asm volatile("cp.async.cg.shared.global [%0], [%1], 16;" :: "r"(dst), "l"(src));
}
__device__ __forceinline__ void cp_commit() {
    asm volatile("cp.async.commit_group;");
}
template<int Np>
__device__ __forceinline__ void cp_wait() {
    asm volatile("cp.async.wait_group %0;" :: "n"(Np));
}
// pack two f32 into f16x2, then exp2 on both halves (one MUFU)
__device__ __forceinline__ unsigned ex2_pack(float lo, float hi) {
    __half2 h = __floats2half2_rn(lo, hi);
    unsigned s = *(unsigned*)&h, p;
    asm("ex2.approx.f16x2 %0, %1;" : "=r"(p) : "r"(s));
    return p;
}

// ---------------------------------------------------------------------------
// pre-pass: fp16 convert (coalesced; no transposes)
// ---------------------------------------------------------------------------
__global__ void cvt_h(const float* __restrict__ in, __half* __restrict__ out, int n4) {
    int i = blockIdx.x * blockDim.x + threadIdx.x;
    if (i < n4) {
        float4 v = ((const float4*)in)[i];
        __half2 h0 = __floats2half2_rn(v.x, v.y);
        __half2 h1 = __floats2half2_rn(v.z, v.w);
        ((uint2*)out)[i] = make_uint2(*(unsigned*)&h0, *(unsigned*)&h1);
    }
}

// ---------------------------------------------------------------------------
// FP16 GEMM + bias (fp32 accumulate). MODE==1: fused per-head RMSNorm, fp16 out.
// C[M,N] = A[M,K] @ W[K,N] + bias ; W row-major (B-frags via ldmatrix.trans).
// CTA 128x128xK64, 256 thr (8 warps, warp 32x64), 3-stage cp.async, 2 CTAs/SM.
// A smem [m][k] stride 72 halves; W smem [k][n] stride 136 halves.
// ---------------------------------------------------------------------------
#define GHS 72
#define BHS 136
#define ASTG (128 * GHS * 2)          // 18432 B / A stage
#define BSTG (64 * BHS * 2)           // 17408 B / W stage
#define GEMM_SMEM (3 * (ASTG + BSTG)) // 107520 B -> 2 CTAs/SM

template<int N, int K, int MODE>
__global__ __launch_bounds__(256, 2) void gemm_f16(
    const __half* __restrict__ A, const __half* __restrict__ W,
    const float* __restrict__ bias, void* __restrict__ Cv,
    const float* __restrict__ q_scale, const float* __restrict__ k_scale)
{
    extern __shared__ __half smh[];
    __half* As = smh;                     // 3 stages x 128*GHS
    __half* Bs = smh + 3 * 128 * GHS;     // 3 stages x 64*BHS

    const int tid = threadIdx.x;
    const int lane = tid & 31;
    const int wid = tid >> 5;
    const int g = lane >> 2;
    const int q = lane & 3;
    const int wm = wid >> 1;              // rows wm*32
    const int wn = wid & 1;               // cols wn*64
    const int bxn = blockIdx.x * 128;
    const int bym = blockIdx.y * 128;

    // A copy: 4 chunks/thread; chunk i => row (tid>>3)+32i, col (tid&7)*8
    const __half* asrc = A + (size_t)(bym + (tid >> 3)) * K + (tid & 7) * 8;
    const unsigned adst = sptr(As) + (((tid >> 3) * GHS + (tid & 7) * 8)) * 2;
    // W copy: 4 chunks/thread; chunk i => k-row (tid>>4)+16i, col (tid&15)*8
    const __half* bsrc = W + (size_t)(tid >> 4) * N + bxn + (tid & 15) * 8;
    const unsigned bdst = sptr(Bs) + (((tid >> 4) * BHS + (tid & 15) * 8)) * 2;

    const unsigned a_base = sptr(As) + ((wm * 32 + (lane & 15)) * GHS) * 2 + (lane >> 4) * 16;
    const unsigned b_base = sptr(Bs)
        + (((lane & 7) + (((lane >> 3) & 1) << 3)) * BHS) * 2 + (lane >> 4) * 16
        + wn * 128;   // wn*64 halves

    float acc[2][8][4];
#pragma unroll
    for (int mf = 0; mf < 2; ++mf)
#pragma unroll
        for (int nf = 0; nf < 8; ++nf)
#pragma unroll
            for (int e = 0; e < 4; ++e) acc[mf][nf][e] = 0.f;

    constexpr int KT = K / 64;

    // prologue: stages 0 and 1
#pragma unroll
    for (int s = 0; s < 2; ++s) {
#pragma unroll
        for (int i = 0; i < 4; ++i) {
            cpa16(adst + s * ASTG + i * (32 * GHS * 2),
                  asrc + (size_t)s * 64 + (size_t)i * (32 * K));
            cpa16(bdst + s * BSTG + i * (16 * BHS * 2),
                  bsrc + (size_t)(s * 64) * N + (size_t)i * (16 * N));
        }
        cp_commit();
    }

#pragma unroll
    for (int kt = 0; kt < KT; ++kt) {
        if (kt + 1 < KT) cp_wait<1>(); else cp_wait<0>();
        __syncthreads();
        if (kt + 2 < KT) {
            const unsigned soA = ((kt + 2) % 3) * ASTG;
            const unsigned soB = ((kt + 2) % 3) * BSTG;
#pragma unroll
            for (int i = 0; i < 4; ++i) {
                cpa16(adst + soA + i * (32 * GHS * 2),
                      asrc + (size_t)(kt + 2) * 64 + (size_t)i * (32 * K));
                cpa16(bdst + soB + i * (16 * BHS * 2),
                      bsrc + (size_t)((kt + 2) * 64) * N + (size_t)i * (16 * N));
            }
            cp_commit();
        }

        const unsigned a_s = a_base + (kt % 3) * ASTG;
        const unsigned b_s = b_base + (kt % 3) * BSTG;
#pragma unroll
        for (int ks = 0; ks < 4; ++ks) {
            unsigned a0[4], a1[4], bl[4][4];
            ldsm4(a0[0], a0[1], a0[2], a0[3], a_s + ks * 32);
            ldsm4(a1[0], a1[1], a1[2], a1[3], a_s + 16 * GHS * 2 + ks * 32);
#pragma unroll
            for (int t2 = 0; t2 < 4; ++t2)
                ldsm4t(bl[t2][0], bl[t2][1], bl[t2][2], bl[t2][3],
                       b_s + ks * (16 * BHS * 2) + t2 * 32);
#pragma unroll
            for (int nf = 0; nf < 8; ++nf) {
                const unsigned* bf = &bl[nf >> 1][(nf & 1) * 2];
                mma_f16(acc[0][nf], a0, bf);
                mma_f16(acc[1][nf], a1, bf);
            }
        }
    }

    // epilogue: bias (+fused rmsnorm), store
    const bool donorm = (MODE == 1) && (bxn < 2048);
    const float* sc = (bxn < 1024) ? q_scale : k_scale;
    const float fold = (bxn < 1024) ? QFOLD : 1.0f;

#pragma unroll
    for (int mf = 0; mf < 2; ++mf) {
        int r0 = bym + wm * 32 + mf * 16 + g;
#pragma unroll
        for (int nf = 0; nf < 8; ++nf) {
            int col = bxn + wn * 64 + nf * 8 + 2 * q;
            float2 bs = *(const float2*)(bias + col);
            acc[mf][nf][0] += bs.x; acc[mf][nf][1] += bs.y;
            acc[mf][nf][2] += bs.x; acc[mf][nf][3] += bs.y;
        }
        if (donorm) {
#pragma unroll
            for (int rh = 0; rh < 2; ++rh) {
                const int e0 = rh * 2, e1 = e0 + 1;
                float ss = 0.f;
#pragma unroll
                for (int nf = 0; nf < 8; ++nf)
                    ss += acc[mf][nf][e0] * acc[mf][nf][e0]
                        + acc[mf][nf][e1] * acc[mf][nf][e1];
                ss += __shfl_xor_sync(0xffffffffu, ss, 1);
                ss += __shfl_xor_sync(0xffffffffu, ss, 2);
                float rr = rsqrtf(ss * (1.0f / HD_) + EPS_) * fold;
#pragma unroll
                for (int nf = 0; nf < 8; ++nf) {
                    float2 s2 = *(const float2*)(sc + nf * 8 + 2 * q);
                    acc[mf][nf][e0] *= rr * s2.x;
                    acc[mf][nf][e1] *= rr * s2.y;
                }
            }
        }
#pragma unroll
        for (int nf = 0; nf < 8; ++nf) {
            int col = bxn + wn * 64 + nf * 8 + 2 * q;
            if (MODE == 1) {
                __half* Ch = (__half*)Cv;
                *(__half2*)(Ch + (size_t)r0 * N + col) =
                    __floats2half2_rn(acc[mf][nf][0], acc[mf][nf][1]);
                *(__half2*)(Ch + (size_t)(r0 + 8) * N + col) =
                    __floats2half2_rn(acc[mf][nf][2], acc[mf][nf][3]);
            } else {
                float* Cf = (float*)Cv;
                *(float2*)(Cf + (size_t)r0 * N + col) =
                    make_float2(acc[mf][nf][0], acc[mf][nf][1]);
                *(float2*)(Cf + (size_t)(r0 + 8) * N + col) =
                    make_float2(acc[mf][nf][2], acc[mf][nf][3]);
            }
        }
    }
}

// ---------------------------------------------------------------------------
// FP16 flash attention, fat warp tile, register-resident P, no online max,
// l via ones-column MMA. NOW 3-stage KV pipeline (wait<1> steady-state).
// 4 warps (128 thr), warp = 32 q x 64 keys, 2 CTAs/SM.
// ---------------------------------------------------------------------------
#define HTS 72
#define OFK (128 * HTS)
#define OFV (OFK + 3 * 64 * HTS)
#define KVSTG (64 * HTS * 2)
#define ATT_SMEM ((OFV + 3 * 64 * HTS) * 2)   // 73728 B -> 2 CTAs/SM

__global__ __launch_bounds__(128, 2) void attn_f16(
    const __half* __restrict__ qkv, __half* __restrict__ o)
{
    extern __shared__ __half smh[];
    __half* Qh = smh;
    __half* Kh = smh + OFK;
    __half* Vh = smh + OFV;

    const int tid = threadIdx.x;
    const int lane = tid & 31;
    const int w = tid >> 5;
    const int g = lane >> 2;
    const int q = lane & 3;
    const int q0 = blockIdx.x * 128;
    const int bh = blockIdx.y;
    const int b = bh >> 4;
    const int h = bh & 15;

    const __half* base = qkv + (size_t)b * S_ * 3 * D_ + h * HD_;

    const int cr = tid >> 3, cc = (tid & 7) * 8;
    const __half* ksrc = base + (size_t)cr * (3 * D_) + D_ + cc;
    const __half* vsrc = base + (size_t)cr * (3 * D_) + 2 * D_ + cc;
    const unsigned kdst = sptr(Kh) + (cr * HTS + cc) * 2;
    const unsigned vdst = sptr(Vh) + (cr * HTS + cc) * 2;

    // prologue: group0 = Q + KV tile0 ; group1 = KV tile1
#pragma unroll
    for (int i = 0; i < 8; ++i)
        cpa16(sptr(Qh) + (cr * HTS + cc) * 2 + i * (16 * HTS * 2),
              base + (size_t)(q0 + cr) * (3 * D_) + cc + (size_t)i * (16 * 3 * D_));
#pragma unroll
    for (int i = 0; i < 4; ++i) {
        cpa16(kdst + i * (16 * HTS * 2), ksrc + (size_t)i * (16 * 3 * D_));
        cpa16(vdst + i * (16 * HTS * 2), vsrc + (size_t)i * (16 * 3 * D_));
    }
    cp_commit();
    {
        const size_t ko = (size_t)64 * (3 * D_);
#pragma unroll
        for (int i = 0; i < 4; ++i) {
            cpa16(kdst + KVSTG + i * (16 * HTS * 2), ksrc + ko + (size_t)i * (16 * 3 * D_));
            cpa16(vdst + KVSTG + i * (16 * HTS * 2), vsrc + ko + (size_t)i * (16 * 3 * D_));
        }
        cp_commit();
    }

    const unsigned qbase = sptr(Qh) + ((w * 32 + (lane & 15)) * HTS) * 2 + (lane >> 4) * 16;
    const unsigned kbase = sptr(Kh)
        + (((lane & 7) + ((lane >> 4) << 3)) * HTS) * 2 + ((lane >> 3) & 1) * 16;
    const unsigned vbase = sptr(Vh)
        + (((lane & 7) + (((lane >> 3) & 1) << 3)) * HTS) * 2 + (lane >> 4) * 16;

    const unsigned ones2[2] = {0x3C003C00u, 0x3C003C00u};

    unsigned qfrag[2][4][4];
    float lacc[2][4] = {{0.f, 0.f, 0.f, 0.f}, {0.f, 0.f, 0.f, 0.f}};
    float acco[2][8][4];
#pragma unroll
    for (int mf = 0; mf < 2; ++mf)
#pragma unroll
        for (int nf = 0; nf < 8; ++nf)
#pragma unroll
            for (int e = 0; e < 4; ++e) acco[mf][nf][e] = 0.f;

    const int T = S_ / 64;
#pragma unroll 3
    for (int t = 0; t < T; ++t) {
        if (t + 1 < T) cp_wait<1>(); else cp_wait<0>();
        __syncthreads();
        if (t + 2 < T) {
            const size_t ko = (size_t)(t + 2) * 64 * (3 * D_);
            const unsigned so = ((t + 2) % 3) * KVSTG;
#pragma unroll
            for (int i = 0; i < 4; ++i) {
                cpa16(kdst + i * (16 * HTS * 2) + so, ksrc + ko + (size_t)i * (16 * 3 * D_));
                cpa16(vdst + i * (16 * HTS * 2) + so, vsrc + ko + (size_t)i * (16 * 3 * D_));
            }
            cp_commit();
        }
        if (t == 0) {   // hoist Q fragments (constant across KV tiles)
#pragma unroll
            for (int mf = 0; mf < 2; ++mf)
#pragma unroll
                for (int ks = 0; ks < 4; ++ks)
                    ldsm4(qfrag[mf][ks][0], qfrag[mf][ks][1],
                          qfrag[mf][ks][2], qfrag[mf][ks][3],
                          qbase + mf * (16 * HTS * 2) + ks * 32);
        }

        const unsigned k_s = kbase + (t % 3) * KVSTG;
        const unsigned v_s = vbase + (t % 3) * KVSTG;

        // S = Q K^T
        float accs[2][8][4];
#pragma unroll
        for (int mf = 0; mf < 2; ++mf)
#pragma unroll
            for (int nf = 0; nf < 8; ++nf)
#pragma unroll
                for (int e = 0; e < 4; ++e) accs[mf][nf][e] = 0.f;
#pragma unroll
        for (int ks = 0; ks < 4; ++ks) {
            unsigned bl[4][4];
#pragma unroll
            for (int t2 = 0; t2 < 4; ++t2)
                ldsm4(bl[t2][0], bl[t2][1], bl[t2][2], bl[t2][3],
                      k_s + t2 * 16 * HTS * 2 + ks * 32);
#pragma unroll
            for (int nf = 0; nf < 8; ++nf) {
                const unsigned* bf = &bl[nf >> 1][(nf & 1) * 2];
                mma_f16(accs[0][nf], qfrag[0][ks], bf);
                mma_f16(accs[1][nf], qfrag[1][ks], bf);
            }
        }

        // p = exp2(s) packed directly as PV A-fragments
        unsigned pa[2][4][4];
#pragma unroll
        for (int mf = 0; mf < 2; ++mf)
#pragma unroll
            for (int j = 0; j < 4; ++j) {
                pa[mf][j][0] = ex2_pack(accs[mf][2 * j][0],     accs[mf][2 * j][1]);
                pa[mf][j][1] = ex2_pack(accs[mf][2 * j][2],     accs[mf][2 * j][3]);
                pa[mf][j][2] = ex2_pack(accs[mf][2 * j + 1][0], accs[mf][2 * j + 1][1]);
                pa[mf][j][3] = ex2_pack(accs[mf][2 * j + 1][2], accs[mf][2 * j + 1][3]);
            }

        // O += P V ; l += P * ones
#pragma unroll
        for (int ks = 0; ks < 4; ++ks) {
            unsigned bl[4][4];
#pragma unroll
            for (int t2 = 0; t2 < 4; ++t2)
                ldsm4t(bl[t2][0], bl[t2][1], bl[t2][2], bl[t2][3],
                       v_s + ks * 16 * HTS * 2 + t2 * 32);
#pragma unroll
            for (int nf = 0; nf < 8; ++nf) {
                const unsigned* bf = &bl[nf >> 1][(nf & 1) * 2];
                mma_f16(acco[0][nf], pa[0][ks], bf);
                mma_f16(acco[1][nf], pa[1][ks], bf);
            }
            mma_f16(lacc[0], pa[0][ks], ones2);
            mma_f16(lacc[1], pa[1][ks], ones2);
        }
    }

    // epilogue: O / l, store fp16
#pragma unroll
    for (int mf = 0; mf < 2; ++mf)
#pragma unroll
    for (int rh = 0; rh < 2; ++rh) {
        float inv = 1.0f / lacc[mf][rh * 2];
        int row = q0 + w * 32 + mf * 16 + g + rh * 8;
        __half* orow = o + (size_t)(b * S_ + row) * D_ + h * HD_;
        const int e0 = rh * 2, e1 = e0 + 1;
#pragma unroll
        for (int nf = 0; nf < 8; ++nf)
            *(__half2*)(orow + nf * 8 + 2 * q) =
                __floats2half2_rn(acco[mf][nf][e0] * inv, acco[mf][nf][e1] * inv);
    }
}

// ---------------------------------------------------------------------------
extern "C" void kernel_launch(void* const* d_in, const int* in_sizes, int n_in,
                              void* d_out, int out_size)
{
    const float* x       = (const float*)d_in[0];
    const float* Wqkv    = (const float*)d_in[1];
    const float* bqkv    = (const float*)d_in[2];
    const float* Wout    = (const float*)d_in[3];
    const float* bout    = (const float*)d_in[4];
    const float* q_scale = (const float*)d_in[5];
    const float* k_scale = (const float*)d_in[6];
    float* out = (float*)d_out;

    __half* qkvh; cudaGetSymbolAddress((void**)&qkvh, g_qkvh);
    __half* oh;   cudaGetSymbolAddress((void**)&oh,   g_oh);
    __half* xh;   cudaGetSymbolAddress((void**)&xh,   g_xh);
    __half* wqh;  cudaGetSymbolAddress((void**)&wqh,  g_wqh);
    __half* woh;  cudaGetSymbolAddress((void**)&woh,  g_woh);

    cudaFuncSetAttribute((const void*)gemm_f16<3 * D_, D_, 1>,
                         cudaFuncAttributeMaxDynamicSharedMemorySize, GEMM_SMEM);
    cudaFuncSetAttribute((const void*)gemm_f16<D_, D_, 0>,
                         cudaFuncAttributeMaxDynamicSharedMemorySize, GEMM_SMEM);
    cudaFuncSetAttribute((const void*)attn_f16,
                         cudaFuncAttributeMaxDynamicSharedMemorySize, ATT_SMEM);

    // 0) pre-convert x + weights to fp16 (all coalesced, no transposes)
    cvt_h<<<(B_ * S_ * D_ / 4 + 255) / 256, 256>>>(x, xh, B_ * S_ * D_ / 4);
    cvt_h<<<(D_ * 3 * D_ / 4 + 255) / 256, 256>>>(Wqkv, wqh, D_ * 3 * D_ / 4);
    cvt_h<<<(D_ * D_ / 4 + 255) / 256, 256>>>(Wout, woh, D_ * D_ / 4);

    // 1) QKV projection + fused RMSNorm, fp16 output
    gemm_f16<3 * D_, D_, 1><<<dim3(3 * D_ / 128, (B_ * S_) / 128), 256, GEMM_SMEM>>>(
        xh, wqh, bqkv, (void*)qkvh, q_scale, k_scale);

    // 2) attention (fat warp tile, register-resident P, 3-stage KV), fp16 out
    attn_f16<<<dim3(S_ / 128, B_ * H_), 128, ATT_SMEM>>>(qkvh, oh);

    // 3) output projection (fp32 output)
    gemm_f16<D_, D_, 0><<<dim3(D_ / 128, (B_ * S_) / 128), 256, GEMM_SMEM>>>(
        oh, woh, bout, (void*)out, q_scale, k_scale);
}

// round 16
// speedup vs baseline: 1.0363x; 1.0363x over previous
#include <cuda_runtime.h>
#include <cuda_fp16.h>
#include <math.h>

#define B_  2
#define S_  2048
#define D_  1024
#define H_  16
#define HD_ 64
#define EPS_ 1e-6f
// (1/sqrt(hd)) * log2(e), folded into q during fused rmsnorm
#define QFOLD 0.18033688011112042f

// Scratch (__device__ globals: allocation-free rule)
__device__ __half g_qkvh[B_ * S_ * 3 * D_];  // qkv fp16 (post-norm q,k)
__device__ __half g_oh [B_ * S_ * D_];       // attention out, fp16
__device__ __half g_xh [B_ * S_ * D_];       // x, fp16
__device__ __half g_wqh[D_ * 3 * D_];        // Wqkv [D][3D] fp16 (row-major)
__device__ __half g_woh[D_ * D_];            // Wout [D][D]  fp16 (row-major)

// ---------------------------------------------------------------------------
__device__ __forceinline__ void mma_f16(float* c, const unsigned* a, const unsigned* b) {
    asm volatile(
        "mma.sync.aligned.m16n8k16.row.col.f32.f16.f16.f32 "
        "{%0,%1,%2,%3}, {%4,%5,%6,%7}, {%8,%9}, {%0,%1,%2,%3};"
        : "+f"(c[0]), "+f"(c[1]), "+f"(c[2]), "+f"(c[3])
        : "r"(a[0]), "r"(a[1]), "r"(a[2]), "r"(a[3]), "r"(b[0]), "r"(b[1]));
}
__device__ __forceinline__ void ldsm4(unsigned& r0, unsigned& r1, unsigned& r2,
                                      unsigned& r3, unsigned addr) {
    asm volatile("ldmatrix.sync.aligned.m8n8.x4.shared.b16 {%0,%1,%2,%3}, [%4];"
        : "=r"(r0), "=r"(r1), "=r"(r2), "=r"(r3) : "r"(addr));
}
__device__ __forceinline__ void ldsm4t(unsigned& r0, unsigned& r1, unsigned& r2,
                                       unsigned& r3, unsigned addr) {
    asm volatile("ldmatrix.sync.aligned.m8n8.x4.trans.shared.b16 {%0,%1,%2,%3}, [%4];"
        : "=r"(r0), "=r"(r1), "=r"(r2), "=r"(r3) : "r"(addr));
}
__device__ __forceinline__ unsigned sptr(const void* p) {
    return (unsigned)__cvta_generic_to_shared(p);
}
__device__ __forceinline__ void cpa16(unsigned dst, const void* src) {
    asm volatile("cp.async.cg.shared.global [%0], [%1], 16;" :: "r"(dst), "l"(src));
}
__device__ __forceinline__ void cp_commit() {
    asm volatile("cp.async.commit_group;");
}
template<int Np>
__device__ __forceinline__ void cp_wait() {
    asm volatile("cp.async.wait_group %0;" :: "n"(Np));
}
// pack two f32 into f16x2, then exp2 on both halves (one MUFU)
__device__ __forceinline__ unsigned ex2_pack(float lo, float hi) {
    __half2 h = __floats2half2_rn(lo, hi);
    unsigned s = *(unsigned*)&h, p;
    asm("ex2.approx.f16x2 %0, %1;" : "=r"(p) : "r"(s));
    return p;
}

// ---------------------------------------------------------------------------
// pre-pass: one fused fp16 conversion over x, Wqkv, Wout (coalesced)
// ---------------------------------------------------------------------------
#define N4_X  (B_ * S_ * D_ / 4)
#define N4_WQ (D_ * 3 * D_ / 4)
#define N4_WO (D_ * D_ / 4)

__global__ void cvt_all(const float* __restrict__ x, __half* __restrict__ xh,
                        const float* __restrict__ wq, __half* __restrict__ wqh,
                        const float* __restrict__ wo, __half* __restrict__ woh)
{
    int i = blockIdx.x * blockDim.x + threadIdx.x;
    const float* in; __half* out; int j;
    if (i < N4_X)                 { in = x;  out = xh;  j = i; }
    else if (i < N4_X + N4_WQ)    { in = wq; out = wqh; j = i - N4_X; }
    else if (i < N4_X + N4_WQ + N4_WO) { in = wo; out = woh; j = i - N4_X - N4_WQ; }
    else return;
    float4 v = ((const float4*)in)[j];
    __half2 h0 = __floats2half2_rn(v.x, v.y);
    __half2 h1 = __floats2half2_rn(v.z, v.w);
    ((uint2*)out)[j] = make_uint2(*(unsigned*)&h0, *(unsigned*)&h1);
}

// ---------------------------------------------------------------------------
// FP16 GEMM + bias (fp32 accumulate). MODE==1: fused per-head RMSNorm, fp16 out.
// C[M,N] = A[M,K] @ W[K,N] + bias ; W row-major (B-frags via ldmatrix.trans).
// CTA 128x128xK64, 256 thr (8 warps, warp 32x64), 3-stage cp.async, 2 CTAs/SM.
// ---------------------------------------------------------------------------
#define GHS 72
#define BHS 136
#define ASTG (128 * GHS * 2)
#define BSTG (64 * BHS * 2)
#define GEMM_SMEM (3 * (ASTG + BSTG))

template<int N, int K, int MODE>
__global__ __launch_bounds__(256, 2) void gemm_f16(
    const __half* __restrict__ A, const __half* __restrict__ W,
    const float* __restrict__ bias, void* __restrict__ Cv,
    const float* __restrict__ q_scale, const float* __restrict__ k_scale)
{
    extern __shared__ __half smh[];
    __half* As = smh;                     // 3 stages x 128*GHS
    __half* Bs = smh + 3 * 128 * GHS;     // 3 stages x 64*BHS

    const int tid = threadIdx.x;
    const int lane = tid & 31;
    const int wid = tid >> 5;
    const int g = lane >> 2;
    const int q = lane & 3;
    const int wm = wid >> 1;
    const int wn = wid & 1;
    const int bxn = blockIdx.x * 128;
    const int bym = blockIdx.y * 128;

    const __half* asrc = A + (size_t)(bym + (tid >> 3)) * K + (tid & 7) * 8;
    const unsigned adst = sptr(As) + (((tid >> 3) * GHS + (tid & 7) * 8)) * 2;
    const __half* bsrc = W + (size_t)(tid >> 4) * N + bxn + (tid & 15) * 8;
    const unsigned bdst = sptr(Bs) + (((tid >> 4) * BHS + (tid & 15) * 8)) * 2;

    const unsigned a_base = sptr(As) + ((wm * 32 + (lane & 15)) * GHS) * 2 + (lane >> 4) * 16;
    const unsigned b_base = sptr(Bs)
        + (((lane & 7) + (((lane >> 3) & 1) << 3)) * BHS) * 2 + (lane >> 4) * 16
        + wn * 128;

    float acc[2][8][4];
#pragma unroll
    for (int mf = 0; mf < 2; ++mf)
#pragma unroll
        for (int nf = 0; nf < 8; ++nf)
#pragma unroll
            for (int e = 0; e < 4; ++e) acc[mf][nf][e] = 0.f;

    constexpr int KT = K / 64;

#pragma unroll
    for (int s = 0; s < 2; ++s) {
#pragma unroll
        for (int i = 0; i < 4; ++i) {
            cpa16(adst + s * ASTG + i * (32 * GHS * 2),
                  asrc + (size_t)s * 64 + (size_t)i * (32 * K));
            cpa16(bdst + s * BSTG + i * (16 * BHS * 2),
                  bsrc + (size_t)(s * 64) * N + (size_t)i * (16 * N));
        }
        cp_commit();
    }

#pragma unroll
    for (int kt = 0; kt < KT; ++kt) {
        if (kt + 1 < KT) cp_wait<1>(); else cp_wait<0>();
        __syncthreads();
        if (kt + 2 < KT) {
            const unsigned soA = ((kt + 2) % 3) * ASTG;
            const unsigned soB = ((kt + 2) % 3) * BSTG;
#pragma unroll
            for (int i = 0; i < 4; ++i) {
                cpa16(adst + soA + i * (32 * GHS * 2),
                      asrc + (size_t)(kt + 2) * 64 + (size_t)i * (32 * K));
                cpa16(bdst + soB + i * (16 * BHS * 2),
                      bsrc + (size_t)((kt + 2) * 64) * N + (size_t)i * (16 * N));
            }
            cp_commit();
        }

        const unsigned a_s = a_base + (kt % 3) * ASTG;
        const unsigned b_s = b_base + (kt % 3) * BSTG;
#pragma unroll
        for (int ks = 0; ks < 4; ++ks) {
            unsigned a0[4], a1[4], bl[4][4];
            ldsm4(a0[0], a0[1], a0[2], a0[3], a_s + ks * 32);
            ldsm4(a1[0], a1[1], a1[2], a1[3], a_s + 16 * GHS * 2 + ks * 32);
#pragma unroll
            for (int t2 = 0; t2 < 4; ++t2)
                ldsm4t(bl[t2][0], bl[t2][1], bl[t2][2], bl[t2][3],
                       b_s + ks * (16 * BHS * 2) + t2 * 32);
#pragma unroll
            for (int nf = 0; nf < 8; ++nf) {
                const unsigned* bf = &bl[nf >> 1][(nf & 1) * 2];
                mma_f16(acc[0][nf], a0, bf);
                mma_f16(acc[1][nf], a1, bf);
            }
        }
    }

    const bool donorm = (MODE == 1) && (bxn < 2048);
    const float* sc = (bxn < 1024) ? q_scale : k_scale;
    const float fold = (bxn < 1024) ? QFOLD : 1.0f;

#pragma unroll
    for (int mf = 0; mf < 2; ++mf) {
        int r0 = bym + wm * 32 + mf * 16 + g;
#pragma unroll
        for (int nf = 0; nf < 8; ++nf) {
            int col = bxn + wn * 64 + nf * 8 + 2 * q;
            float2 bs = *(const float2*)(bias + col);
            acc[mf][nf][0] += bs.x; acc[mf][nf][1] += bs.y;
            acc[mf][nf][2] += bs.x; acc[mf][nf][3] += bs.y;
        }
        if (donorm) {
#pragma unroll
            for (int rh = 0; rh < 2; ++rh) {
                const int e0 = rh * 2, e1 = e0 + 1;
                float ss = 0.f;
#pragma unroll
                for (int nf = 0; nf < 8; ++nf)
                    ss += acc[mf][nf][e0] * acc[mf][nf][e0]
                        + acc[mf][nf][e1] * acc[mf][nf][e1];
                ss += __shfl_xor_sync(0xffffffffu, ss, 1);
                ss += __shfl_xor_sync(0xffffffffu, ss, 2);
                float rr = rsqrtf(ss * (1.0f / HD_) + EPS_) * fold;
#pragma unroll
                for (int nf = 0; nf < 8; ++nf) {
                    float2 s2 = *(const float2*)(sc + nf * 8 + 2 * q);
                    acc[mf][nf][e0] *= rr * s2.x;
                    acc[mf][nf][e1] *= rr * s2.y;
                }
            }
        }
#pragma unroll
        for (int nf = 0; nf < 8; ++nf) {
            int col = bxn + wn * 64 + nf * 8 + 2 * q;
            if (MODE == 1) {
                __half* Ch = (__half*)Cv;
                *(__half2*)(Ch + (size_t)r0 * N + col) =
                    __floats2half2_rn(acc[mf][nf][0], acc[mf][nf][1]);
                *(__half2*)(Ch + (size_t)(r0 + 8) * N + col) =
                    __floats2half2_rn(acc[mf][nf][2], acc[mf][nf][3]);
            } else {
                float* Cf = (float*)Cv;
                *(float2*)(Cf + (size_t)r0 * N + col) =
                    make_float2(acc[mf][nf][0], acc[mf][nf][1]);
                *(float2*)(Cf + (size_t)(r0 + 8) * N + col) =
                    make_float2(acc[mf][nf][2], acc[mf][nf][3]);
            }
        }
    }
}

// ---------------------------------------------------------------------------
// FP16 flash attention — exact round-13 kernel (2-stage KV, fat warp tile,
// register-resident P, no online max, l via ones-column MMA). Measured best.
// ---------------------------------------------------------------------------
#define HTS 72
#define OFK (128 * HTS)
#define OFV (OFK + 2 * 64 * HTS)
#define KVSTG (64 * HTS * 2)
#define ATT_SMEM ((OFV + 2 * 64 * HTS) * 2)   // 55296 B

__global__ __launch_bounds__(128, 2) void attn_f16(
    const __half* __restrict__ qkv, __half* __restrict__ o)
{
    extern __shared__ __half smh[];
    __half* Qh = smh;
    __half* Kh = smh + OFK;
    __half* Vh = smh + OFV;

    const int tid = threadIdx.x;
    const int lane = tid & 31;
    const int w = tid >> 5;
    const int g = lane >> 2;
    const int q = lane & 3;
    const int q0 = blockIdx.x * 128;
    const int bh = blockIdx.y;
    const int b = bh >> 4;
    const int h = bh & 15;

    const __half* base = qkv + (size_t)b * S_ * 3 * D_ + h * HD_;

    const int cr = tid >> 3, cc = (tid & 7) * 8;
    const __half* ksrc = base + (size_t)cr * (3 * D_) + D_ + cc;
    const __half* vsrc = base + (size_t)cr * (3 * D_) + 2 * D_ + cc;
    const unsigned kdst = sptr(Kh) + (cr * HTS + cc) * 2;
    const unsigned vdst = sptr(Vh) + (cr * HTS + cc) * 2;

#pragma unroll
    for (int i = 0; i < 8; ++i)
        cpa16(sptr(Qh) + (cr * HTS + cc) * 2 + i * (16 * HTS * 2),
              base + (size_t)(q0 + cr) * (3 * D_) + cc + (size_t)i * (16 * 3 * D_));
#pragma unroll
    for (int i = 0; i < 4; ++i) {
        cpa16(kdst + i * (16 * HTS * 2), ksrc + (size_t)i * (16 * 3 * D_));
        cpa16(vdst + i * (16 * HTS * 2), vsrc + (size_t)i * (16 * 3 * D_));
    }
    cp_commit();

    const unsigned qbase = sptr(Qh) + ((w * 32 + (lane & 15)) * HTS) * 2 + (lane >> 4) * 16;
    const unsigned kbase = sptr(Kh)
        + (((lane & 7) + ((lane >> 4) << 3)) * HTS) * 2 + ((lane >> 3) & 1) * 16;
    const unsigned vbase = sptr(Vh)
        + (((lane & 7) + (((lane >> 3) & 1) << 3)) * HTS) * 2 + (lane >> 4) * 16;

    const unsigned ones2[2] = {0x3C003C00u, 0x3C003C00u};

    unsigned qfrag[2][4][4];
    float lacc[2][4] = {{0.f, 0.f, 0.f, 0.f}, {0.f, 0.f, 0.f, 0.f}};
    float acco[2][8][4];
#pragma unroll
    for (int mf = 0; mf < 2; ++mf)
#pragma unroll
        for (int nf = 0; nf < 8; ++nf)
#pragma unroll
            for (int e = 0; e < 4; ++e) acco[mf][nf][e] = 0.f;

    const int T = S_ / 64;
#pragma unroll 2
    for (int t = 0; t < T; ++t) {
        cp_wait<0>();
        __syncthreads();
        if (t + 1 < T) {
            const size_t ko = (size_t)(t + 1) * 64 * (3 * D_);
            const unsigned so = ((t + 1) & 1) * KVSTG;
#pragma unroll
            for (int i = 0; i < 4; ++i) {
                cpa16(kdst + i * (16 * HTS * 2) + so, ksrc + ko + (size_t)i * (16 * 3 * D_));
                cpa16(vdst + i * (16 * HTS * 2) + so, vsrc + ko + (size_t)i * (16 * 3 * D_));
            }
            cp_commit();
        }
        if (t == 0) {
#pragma unroll
            for (int mf = 0; mf < 2; ++mf)
#pragma unroll
                for (int ks = 0; ks < 4; ++ks)
                    ldsm4(qfrag[mf][ks][0], qfrag[mf][ks][1],
                          qfrag[mf][ks][2], qfrag[mf][ks][3],
                          qbase + mf * (16 * HTS * 2) + ks * 32);
        }

        const unsigned k_s = kbase + (t & 1) * KVSTG;
        const unsigned v_s = vbase + (t & 1) * KVSTG;

        float accs[2][8][4];
#pragma unroll
        for (int mf = 0; mf < 2; ++mf)
#pragma unroll
            for (int nf = 0; nf < 8; ++nf)
#pragma unroll
                for (int e = 0; e < 4; ++e) accs[mf][nf][e] = 0.f;
#pragma unroll
        for (int ks = 0; ks < 4; ++ks) {
            unsigned bl[4][4];
#pragma unroll
            for (int t2 = 0; t2 < 4; ++t2)
                ldsm4(bl[t2][0], bl[t2][1], bl[t2][2], bl[t2][3],
                      k_s + t2 * 16 * HTS * 2 + ks * 32);
#pragma unroll
            for (int nf = 0; nf < 8; ++nf) {
                const unsigned* bf = &bl[nf >> 1][(nf & 1) * 2];
                mma_f16(accs[0][nf], qfrag[0][ks], bf);
                mma_f16(accs[1][nf], qfrag[1][ks], bf);
            }
        }

        unsigned pa[2][4][4];
#pragma unroll
        for (int mf = 0; mf < 2; ++mf)
#pragma unroll
            for (int j = 0; j < 4; ++j) {
                pa[mf][j][0] = ex2_pack(accs[mf][2 * j][0],     accs[mf][2 * j][1]);
                pa[mf][j][1] = ex2_pack(accs[mf][2 * j][2],     accs[mf][2 * j][3]);
                pa[mf][j][2] = ex2_pack(accs[mf][2 * j + 1][0], accs[mf][2 * j + 1][1]);
                pa[mf][j][3] = ex2_pack(accs[mf][2 * j + 1][2], accs[mf][2 * j + 1][3]);
            }

#pragma unroll
        for (int ks = 0; ks < 4; ++ks) {
            unsigned bl[4][4];
#pragma unroll
            for (int t2 = 0; t2 < 4; ++t2)
                ldsm4t(bl[t2][0], bl[t2][1], bl[t2][2], bl[t2][3],
                       v_s + ks * 16 * HTS * 2 + t2 * 32);
#pragma unroll
            for (int nf = 0; nf < 8; ++nf) {
                const unsigned* bf = &bl[nf >> 1][(nf & 1) * 2];
                mma_f16(acco[0][nf], pa[0][ks], bf);
                mma_f16(acco[1][nf], pa[1][ks], bf);
            }
            mma_f16(lacc[0], pa[0][ks], ones2);
            mma_f16(lacc[1], pa[1][ks], ones2);
        }
    }

#pragma unroll
    for (int mf = 0; mf < 2; ++mf)
#pragma unroll
    for (int rh = 0; rh < 2; ++rh) {
        float inv = 1.0f / lacc[mf][rh * 2];
        int row = q0 + w * 32 + mf * 16 + g + rh * 8;
        __half* orow = o + (size_t)(b * S_ + row) * D_ + h * HD_;
        const int e0 = rh * 2, e1 = e0 + 1;
#pragma unroll
        for (int nf = 0; nf < 8; ++nf)
            *(__half2*)(orow + nf * 8 + 2 * q) =
                __floats2half2_rn(acco[mf][nf][e0] * inv, acco[mf][nf][e1] * inv);
    }
}

// ---------------------------------------------------------------------------
extern "C" void kernel_launch(void* const* d_in, const int* in_sizes, int n_in,
                              void* d_out, int out_size)
{
    const float* x       = (const float*)d_in[0];
    const float* Wqkv    = (const float*)d_in[1];
    const float* bqkv    = (const float*)d_in[2];
    const float* Wout    = (const float*)d_in[3];
    const float* bout    = (const float*)d_in[4];
    const float* q_scale = (const float*)d_in[5];
    const float* k_scale = (const float*)d_in[6];
    float* out = (float*)d_out;

    __half* qkvh; cudaGetSymbolAddress((void**)&qkvh, g_qkvh);
    __half* oh;   cudaGetSymbolAddress((void**)&oh,   g_oh);
    __half* xh;   cudaGetSymbolAddress((void**)&xh,   g_xh);
    __half* wqh;  cudaGetSymbolAddress((void**)&wqh,  g_wqh);
    __half* woh;  cudaGetSymbolAddress((void**)&woh,  g_woh);

    cudaFuncSetAttribute((const void*)gemm_f16<3 * D_, D_, 1>,
                         cudaFuncAttributeMaxDynamicSharedMemorySize, GEMM_SMEM);
    cudaFuncSetAttribute((const void*)gemm_f16<D_, D_, 0>,
                         cudaFuncAttributeMaxDynamicSharedMemorySize, GEMM_SMEM);
    cudaFuncSetAttribute((const void*)attn_f16,
                         cudaFuncAttributeMaxDynamicSharedMemorySize, ATT_SMEM);

    // 0) single fused fp16 conversion (x + both weights, coalesced)
    {
        const int total = N4_X + N4_WQ + N4_WO;
        cvt_all<<<(total + 255) / 256, 256>>>(x, xh, Wqkv, wqh, Wout, woh);
    }

    // 1) QKV projection + fused RMSNorm, fp16 output
    gemm_f16<3 * D_, D_, 1><<<dim3(3 * D_ / 128, (B_ * S_) / 128), 256, GEMM_SMEM>>>(
        xh, wqh, bqkv, (void*)qkvh, q_scale, k_scale);

    // 2) attention (round-13 kernel, measured best), fp16 output
    attn_f16<<<dim3(S_ / 128, B_ * H_), 128, ATT_SMEM>>>(qkvh, oh);

    // 3) output projection (fp32 output)
    gemm_f16<D_, D_, 0><<<dim3(D_ / 128, (B_ * S_) / 128), 256, GEMM_SMEM>>>(
        oh, woh, bout, (void*)out, q_scale, k_scale);
}